// round 2
// baseline (speedup 1.0000x reference)
#include <cuda_runtime.h>
#include <stdint.h>

#define D 64
#define N_MAX 100096

// ---------------- scratch (no allocations allowed) ----------------
__device__ __align__(16) float g_agg[(size_t)N_MAX * D];
__device__ float g_dis[N_MAX];
__device__ int   g_cnt[N_MAX];
__device__ __align__(16) float g_sum[D];
__device__ __align__(16) float g_sq[D];
__device__ __align__(16) float g_scale[D];
__device__ __align__(16) float g_shift[D];
__device__ int   g_is64;   // 1 if edge_index buffer is int64, 0 if int32

// ---------------- edge index accessor (dtype-robust) ----------------
__device__ __forceinline__ int edge_idx(const void* ei, int half, int E, int e, int is64) {
    if (is64) return (int)((const long long*)ei)[(size_t)half * E + e];
    return ((const int*)ei)[(size_t)half * E + e];
}

// ---------------- K-1: detect edge dtype ----------------
// int64 non-negative indices < 2^31 have zero high words; int32 random
// indices make the odd words nonzero with overwhelming probability.
__global__ void k_detect(const unsigned int* __restrict__ w) {
    if (threadIdx.x == 0) {
        int all0 = 1;
        #pragma unroll
        for (int i = 0; i < 32; i++)
            if (w[2 * i + 1] != 0u) { all0 = 0; break; }
        g_is64 = all0;
    }
}

// ---------------- K0: zero counters + BN accumulators ----------------
__global__ void k_zero(int n) {
    int i = blockIdx.x * blockDim.x + threadIdx.x;
    if (i < n) g_cnt[i] = 0;
    if (i < D) { g_sum[i] = 0.f; g_sq[i] = 0.f; }
}

// ---------------- K1: degree over rows ----------------
__global__ void k_degree(const void* __restrict__ ei, int E, int n) {
    int e = blockIdx.x * blockDim.x + threadIdx.x;
    if (e >= E) return;
    int is64 = g_is64;
    int r = edge_idx(ei, 0, E, e, is64);
    if ((unsigned)r < (unsigned)n) atomicAdd(&g_cnt[r], 1);
}

// ---------------- K2: dis = rsqrt(1+cnt); agg = dis^2 * x ----------------
__global__ void k_init(const float* __restrict__ x, int n) {
    int t = blockIdx.x * blockDim.x + threadIdx.x;
    if (t >= n * 16) return;
    int node = t >> 4;
    int c    = t & 15;
    float dval = rsqrtf(1.0f + (float)g_cnt[node]);
    if (c == 0) g_dis[node] = dval;
    float s = dval * dval;
    float4 v = ((const float4*)x)[t];
    ((float4*)g_agg)[t] = make_float4(s * v.x, s * v.y, s * v.z, s * v.w);
}

// ---------------- K3: edge scatter-add (SpMM), 16 threads/edge ----------------
__global__ void k_spmm(const float* __restrict__ x,
                       const void* __restrict__ ei,
                       int E, int n) {
    int t = blockIdx.x * blockDim.x + threadIdx.x;
    if (t >= E * 16) return;
    int e = t >> 4;
    int c = t & 15;
    int is64 = g_is64;
    int r  = edge_idx(ei, 0, E, e, is64);
    int cc = edge_idx(ei, 1, E, e, is64);
    if ((unsigned)r >= (unsigned)n || (unsigned)cc >= (unsigned)n) return;
    float nrm = g_dis[r] * g_dis[cc];
    float4 v = __ldg(((const float4*)x) + (size_t)cc * 16 + c);
    float4 m = make_float4(nrm * v.x, nrm * v.y, nrm * v.z, nrm * v.w);
    float* dst = g_agg + (size_t)r * D + c * 4;
    asm volatile("red.global.add.v4.f32 [%0], {%1,%2,%3,%4};"
                 :: "l"(dst), "f"(m.x), "f"(m.y), "f"(m.z), "f"(m.w)
                 : "memory");
}

// ---------------- K4: y = relu(agg @ W^T + b) + BN partials ----------------
#define SA_STRIDE 68
__global__ void __launch_bounds__(256)
k_gemm(const float* __restrict__ W, const float* __restrict__ bias,
       float* __restrict__ out, int n) {
    __shared__ float sw[D * D];
    __shared__ float sa[D * SA_STRIDE];
    __shared__ float2 spart[16][D];

    int t  = threadIdx.x;
    int r0 = blockIdx.x * 64;

    #pragma unroll
    for (int i = t; i < D * D; i += 256) {
        int j = i >> 6, k = i & 63;
        sw[k * D + j] = W[i];
    }
    #pragma unroll
    for (int i = t; i < D * D; i += 256) {
        int r = i >> 6, k = i & 63;
        sa[r * SA_STRIDE + k] = (r0 + r < n) ? g_agg[(size_t)(r0 + r) * D + k] : 0.f;
    }
    __syncthreads();

    int tj = t & 15;
    int ti = t >> 4;
    float acc[4][4];
    #pragma unroll
    for (int m = 0; m < 4; m++)
        #pragma unroll
        for (int q = 0; q < 4; q++) acc[m][q] = 0.f;

    #pragma unroll 4
    for (int k = 0; k < D; k++) {
        float4 w4 = *(const float4*)&sw[k * D + tj * 4];
        float a0 = sa[(ti     ) * SA_STRIDE + k];
        float a1 = sa[(ti + 16) * SA_STRIDE + k];
        float a2 = sa[(ti + 32) * SA_STRIDE + k];
        float a3 = sa[(ti + 48) * SA_STRIDE + k];
        acc[0][0] += a0 * w4.x; acc[0][1] += a0 * w4.y; acc[0][2] += a0 * w4.z; acc[0][3] += a0 * w4.w;
        acc[1][0] += a1 * w4.x; acc[1][1] += a1 * w4.y; acc[1][2] += a1 * w4.z; acc[1][3] += a1 * w4.w;
        acc[2][0] += a2 * w4.x; acc[2][1] += a2 * w4.y; acc[2][2] += a2 * w4.z; acc[2][3] += a2 * w4.w;
        acc[3][0] += a3 * w4.x; acc[3][1] += a3 * w4.y; acc[3][2] += a3 * w4.z; acc[3][3] += a3 * w4.w;
    }

    float4 b4 = *(const float4*)&bias[tj * 4];
    float csum[4] = {0.f, 0.f, 0.f, 0.f};
    float csq[4]  = {0.f, 0.f, 0.f, 0.f};

    #pragma unroll
    for (int m = 0; m < 4; m++) {
        int row = r0 + ti + 16 * m;
        if (row < n) {
            float4 y;
            y.x = fmaxf(acc[m][0] + b4.x, 0.f);
            y.y = fmaxf(acc[m][1] + b4.y, 0.f);
            y.z = fmaxf(acc[m][2] + b4.z, 0.f);
            y.w = fmaxf(acc[m][3] + b4.w, 0.f);
            *(float4*)(out + (size_t)row * D + tj * 4) = y;
            csum[0] += y.x; csq[0] += y.x * y.x;
            csum[1] += y.y; csq[1] += y.y * y.y;
            csum[2] += y.z; csq[2] += y.z * y.z;
            csum[3] += y.w; csq[3] += y.w * y.w;
        }
    }
    #pragma unroll
    for (int q = 0; q < 4; q++)
        spart[ti][tj * 4 + q] = make_float2(csum[q], csq[q]);
    __syncthreads();

    if (t < D) {
        float s = 0.f, s2 = 0.f;
        #pragma unroll
        for (int g = 0; g < 16; g++) {
            float2 p = spart[g][t];
            s += p.x; s2 += p.y;
        }
        atomicAdd(&g_sum[t], s);
        atomicAdd(&g_sq[t], s2);
    }
}

// ---------------- K5: BN stats ----------------
__global__ void k_stats(const float* __restrict__ gamma,
                        const float* __restrict__ beta, float invN) {
    int j = threadIdx.x;
    float mean = g_sum[j] * invN;
    float var  = g_sq[j] * invN - mean * mean;
    float sc   = gamma[j] * rsqrtf(var + 1e-5f);
    g_scale[j] = sc;
    g_shift[j] = beta[j] - mean * sc;
}

// ---------------- K6: in-place normalize ----------------
__global__ void k_norm(float* __restrict__ out, int n) {
    int t = blockIdx.x * blockDim.x + threadIdx.x;
    if (t >= n * 16) return;
    int c = t & 15;
    float4 v  = ((float4*)out)[t];
    float4 sc = ((const float4*)g_scale)[c];
    float4 sh = ((const float4*)g_shift)[c];
    v.x = v.x * sc.x + sh.x;
    v.y = v.y * sc.y + sh.y;
    v.z = v.z * sc.z + sh.z;
    v.w = v.w * sc.w + sh.w;
    ((float4*)out)[t] = v;
}

// ---------------- launch ----------------
extern "C" void kernel_launch(void* const* d_in, const int* in_sizes, int n_in,
                              void* d_out, int out_size) {
    const float* x     = (const float*)d_in[0];
    const void*  ei    = d_in[1];
    const float* W     = (const float*)d_in[2];
    const float* bias  = (const float*)d_in[3];
    const float* gamma = (const float*)d_in[4];
    const float* beta  = (const float*)d_in[5];
    float*       out   = (float*)d_out;

    int n = in_sizes[0] / D;        // 100000
    int E = in_sizes[1] / 2;        // 1200000 (element count is 2*E either dtype)

    k_detect<<<1, 32>>>((const unsigned int*)ei);
    k_zero  <<<(n + 255) / 256, 256>>>(n);
    k_degree<<<(E + 255) / 256, 256>>>(ei, E, n);
    k_init  <<<(n * 16 + 255) / 256, 256>>>(x, n);
    k_spmm  <<<(E * 16 + 255) / 256, 256>>>(x, ei, E, n);
    k_gemm  <<<(n + 63) / 64, 256>>>(W, bias, out, n);
    k_stats <<<1, D>>>(gamma, beta, 1.0f / (float)n);
    k_norm  <<<(n * 16 + 255) / 256, 256>>>(out, n);
}

// round 3
// speedup vs baseline: 1.2375x; 1.2375x over previous
#include <cuda_runtime.h>
#include <stdint.h>

#define D 64
#define N_MAX 100096
#define E_MAX 1310720

// ---------------- scratch ----------------
__device__ __align__(16) float g_agg[(size_t)N_MAX * D];
__device__ float g_dis[N_MAX];
__device__ int   g_cnt[N_MAX];
__device__ int   g_off[N_MAX + 1];   // CSR row offsets
__device__ int   g_woff[N_MAX];      // working copy for scatter
__device__ int   g_ecol[E_MAX];      // CSR column indices
__device__ int   g_bsum[512];        // block partial sums for scan
__device__ int   g_boff[512];        // exclusive block offsets
__device__ __align__(16) float g_sum[D];
__device__ __align__(16) float g_sq[D];
__device__ __align__(16) float g_scale[D];
__device__ __align__(16) float g_shift[D];
__device__ int   g_is64;

// ---------------- edge index accessor (dtype-robust) ----------------
__device__ __forceinline__ int edge_idx(const void* ei, int half, int E, int e, int is64) {
    if (is64) return (int)((const long long*)ei)[(size_t)half * E + e];
    return ((const int*)ei)[(size_t)half * E + e];
}

// ---------------- K0: zero counters + BN accum + dtype detect ----------------
__global__ void k_zero(const unsigned int* __restrict__ w, int n) {
    int i = blockIdx.x * blockDim.x + threadIdx.x;
    if (i < n) g_cnt[i] = 0;
    if (i < D) { g_sum[i] = 0.f; g_sq[i] = 0.f; }
    if (blockIdx.x == 0 && threadIdx.x == 0) {
        int all0 = 1;
        #pragma unroll
        for (int k = 0; k < 32; k++)
            if (w[2 * k + 1] != 0u) { all0 = 0; break; }
        g_is64 = all0;
    }
}

// ---------------- K1: degree over rows ----------------
__global__ void k_degree(const void* __restrict__ ei, int E, int n) {
    int e = blockIdx.x * blockDim.x + threadIdx.x;
    if (e >= E) return;
    int r = edge_idx(ei, 0, E, e, g_is64);
    if ((unsigned)r < (unsigned)n) atomicAdd(&g_cnt[r], 1);
}

// ---------------- K2a: per-block partial sums of g_cnt ----------------
__global__ void k_bsum(int n) {
    __shared__ int s[256];
    int i = blockIdx.x * 256 + threadIdx.x;
    s[threadIdx.x] = (i < n) ? g_cnt[i] : 0;
    __syncthreads();
    #pragma unroll
    for (int o = 128; o > 0; o >>= 1) {
        if (threadIdx.x < o) s[threadIdx.x] += s[threadIdx.x + o];
        __syncthreads();
    }
    if (threadIdx.x == 0) g_bsum[blockIdx.x] = s[0];
}

// ---------------- K2b: scan block sums (single block, 512 threads) --------
__global__ void k_bscan(int nb, int n) {
    __shared__ int s[512];
    int t = threadIdx.x;
    s[t] = (t < nb) ? g_bsum[t] : 0;
    __syncthreads();
    #pragma unroll
    for (int o = 1; o < 512; o <<= 1) {
        int v = (t >= o) ? s[t - o] : 0;
        __syncthreads();
        s[t] += v;
        __syncthreads();
    }
    if (t < nb) g_boff[t] = (t == 0) ? 0 : s[t - 1];
    if (t == 0) g_off[n] = s[511];
}

// ---------------- K2c: apply scan -> g_off/g_woff, compute g_dis ----------
__global__ void k_apply(int n) {
    __shared__ int s[256];
    int t = threadIdx.x;
    int i = blockIdx.x * 256 + t;
    int c = (i < n) ? g_cnt[i] : 0;
    s[t] = c;
    __syncthreads();
    #pragma unroll
    for (int o = 1; o < 256; o <<= 1) {
        int v = (t >= o) ? s[t - o] : 0;
        __syncthreads();
        s[t] += v;
        __syncthreads();
    }
    if (i < n) {
        int off = g_boff[blockIdx.x] + s[t] - c;   // exclusive
        g_off[i]  = off;
        g_woff[i] = off;
        g_dis[i]  = rsqrtf(1.0f + (float)c);
    }
}

// ---------------- K3: scatter edges into CSR ----------------
__global__ void k_scatter(const void* __restrict__ ei, int E, int n) {
    int e = blockIdx.x * blockDim.x + threadIdx.x;
    if (e >= E) return;
    int is64 = g_is64;
    int r  = edge_idx(ei, 0, E, e, is64);
    int cc = edge_idx(ei, 1, E, e, is64);
    if ((unsigned)r >= (unsigned)n || (unsigned)cc >= (unsigned)n) return;
    int pos = atomicAdd(&g_woff[r], 1);
    g_ecol[pos] = cc;
}

// ---------------- K4: pull-mode SpMM (CSR), 16 threads/node ----------------
__global__ void __launch_bounds__(256)
k_spmm(const float* __restrict__ x, int n) {
    int t = blockIdx.x * blockDim.x + threadIdx.x;
    int node = t >> 4;
    int c    = t & 15;
    if (node >= n) return;
    float di = g_dis[node];
    int start = g_off[node];
    int end   = g_off[node + 1];
    // self-loop: dis^2 * x[i]; factor one dis out -> final scale
    float4 xv  = __ldg((const float4*)x + (size_t)node * 16 + c);
    float4 acc = make_float4(di * xv.x, di * xv.y, di * xv.z, di * xv.w);
    for (int k = start; k < end; k++) {
        int cc   = g_ecol[k];             // broadcast within 16-thread group
        float dc = g_dis[cc];             // broadcast
        float4 v = __ldg((const float4*)x + (size_t)cc * 16 + c);
        acc.x += dc * v.x;
        acc.y += dc * v.y;
        acc.z += dc * v.z;
        acc.w += dc * v.w;
    }
    acc.x *= di; acc.y *= di; acc.z *= di; acc.w *= di;
    ((float4*)g_agg)[(size_t)node * 16 + c] = acc;
}

// ---------------- K5: y = relu(agg @ W^T + b) + BN partials ----------------
#define SA_STRIDE 68
__global__ void __launch_bounds__(256)
k_gemm(const float* __restrict__ W, const float* __restrict__ bias,
       float* __restrict__ out, int n) {
    __shared__ float sw[D * D];
    __shared__ float sa[D * SA_STRIDE];
    __shared__ float2 spart[16][D];

    int t  = threadIdx.x;
    int r0 = blockIdx.x * 64;

    #pragma unroll
    for (int i = t; i < D * D; i += 256) {
        int j = i >> 6, k = i & 63;
        sw[k * D + j] = W[i];
    }
    #pragma unroll
    for (int i = t; i < D * D; i += 256) {
        int r = i >> 6, k = i & 63;
        sa[r * SA_STRIDE + k] = (r0 + r < n) ? g_agg[(size_t)(r0 + r) * D + k] : 0.f;
    }
    __syncthreads();

    int tj = t & 15;
    int ti = t >> 4;
    float acc[4][4];
    #pragma unroll
    for (int m = 0; m < 4; m++)
        #pragma unroll
        for (int q = 0; q < 4; q++) acc[m][q] = 0.f;

    #pragma unroll 4
    for (int k = 0; k < D; k++) {
        float4 w4 = *(const float4*)&sw[k * D + tj * 4];
        float a0 = sa[(ti     ) * SA_STRIDE + k];
        float a1 = sa[(ti + 16) * SA_STRIDE + k];
        float a2 = sa[(ti + 32) * SA_STRIDE + k];
        float a3 = sa[(ti + 48) * SA_STRIDE + k];
        acc[0][0] += a0 * w4.x; acc[0][1] += a0 * w4.y; acc[0][2] += a0 * w4.z; acc[0][3] += a0 * w4.w;
        acc[1][0] += a1 * w4.x; acc[1][1] += a1 * w4.y; acc[1][2] += a1 * w4.z; acc[1][3] += a1 * w4.w;
        acc[2][0] += a2 * w4.x; acc[2][1] += a2 * w4.y; acc[2][2] += a2 * w4.z; acc[2][3] += a2 * w4.w;
        acc[3][0] += a3 * w4.x; acc[3][1] += a3 * w4.y; acc[3][2] += a3 * w4.z; acc[3][3] += a3 * w4.w;
    }

    float4 b4 = *(const float4*)&bias[tj * 4];
    float csum[4] = {0.f, 0.f, 0.f, 0.f};
    float csq[4]  = {0.f, 0.f, 0.f, 0.f};

    #pragma unroll
    for (int m = 0; m < 4; m++) {
        int row = r0 + ti + 16 * m;
        if (row < n) {
            float4 y;
            y.x = fmaxf(acc[m][0] + b4.x, 0.f);
            y.y = fmaxf(acc[m][1] + b4.y, 0.f);
            y.z = fmaxf(acc[m][2] + b4.z, 0.f);
            y.w = fmaxf(acc[m][3] + b4.w, 0.f);
            *(float4*)(out + (size_t)row * D + tj * 4) = y;
            csum[0] += y.x; csq[0] += y.x * y.x;
            csum[1] += y.y; csq[1] += y.y * y.y;
            csum[2] += y.z; csq[2] += y.z * y.z;
            csum[3] += y.w; csq[3] += y.w * y.w;
        }
    }
    #pragma unroll
    for (int q = 0; q < 4; q++)
        spart[ti][tj * 4 + q] = make_float2(csum[q], csq[q]);
    __syncthreads();

    if (t < D) {
        float s = 0.f, s2 = 0.f;
        #pragma unroll
        for (int g = 0; g < 16; g++) {
            float2 p = spart[g][t];
            s += p.x; s2 += p.y;
        }
        atomicAdd(&g_sum[t], s);
        atomicAdd(&g_sq[t], s2);
    }
}

// ---------------- K6: BN stats ----------------
__global__ void k_stats(const float* __restrict__ gamma,
                        const float* __restrict__ beta, float invN) {
    int j = threadIdx.x;
    float mean = g_sum[j] * invN;
    float var  = g_sq[j] * invN - mean * mean;
    float sc   = gamma[j] * rsqrtf(var + 1e-5f);
    g_scale[j] = sc;
    g_shift[j] = beta[j] - mean * sc;
}

// ---------------- K7: in-place normalize ----------------
__global__ void k_norm(float* __restrict__ out, int n) {
    int t = blockIdx.x * blockDim.x + threadIdx.x;
    if (t >= n * 16) return;
    int c = t & 15;
    float4 v  = ((float4*)out)[t];
    float4 sc = ((const float4*)g_scale)[c];
    float4 sh = ((const float4*)g_shift)[c];
    v.x = v.x * sc.x + sh.x;
    v.y = v.y * sc.y + sh.y;
    v.z = v.z * sc.z + sh.z;
    v.w = v.w * sc.w + sh.w;
    ((float4*)out)[t] = v;
}

// ---------------- launch ----------------
extern "C" void kernel_launch(void* const* d_in, const int* in_sizes, int n_in,
                              void* d_out, int out_size) {
    const float* x     = (const float*)d_in[0];
    const void*  ei    = d_in[1];
    const float* W     = (const float*)d_in[2];
    const float* bias  = (const float*)d_in[3];
    const float* gamma = (const float*)d_in[4];
    const float* beta  = (const float*)d_in[5];
    float*       out   = (float*)d_out;

    int n  = in_sizes[0] / D;     // 100000
    int E  = in_sizes[1] / 2;     // 1200000
    int nb = (n + 255) / 256;     // 391 blocks for scan

    k_zero   <<<nb, 256>>>((const unsigned int*)ei, n);
    k_degree <<<(E + 255) / 256, 256>>>(ei, E, n);
    k_bsum   <<<nb, 256>>>(n);
    k_bscan  <<<1, 512>>>(nb, n);
    k_apply  <<<nb, 256>>>(n);
    k_scatter<<<(E + 255) / 256, 256>>>(ei, E, n);
    k_spmm   <<<(n * 16 + 255) / 256, 256>>>(x, n);
    k_gemm   <<<(n + 63) / 64, 256>>>(W, bias, out, n);
    k_stats  <<<1, D>>>(gamma, beta, 1.0f / (float)n);
    k_norm   <<<(n * 16 + 255) / 256, 256>>>(out, n);
}